// round 7
// baseline (speedup 1.0000x reference)
#include <cuda_runtime.h>
#include <cstddef>

// Eq1to3: out[n,s,i,j,k] = Yi[n,s,i] + Yj[n,s,j] + Yk[n,s,k] + S[n,s] + bias[s]
//
// Two-kernel split with working PDL overlap + 256-bit streaming stores:
//   1) precompute_kernel: fires the PDL trigger immediately, then
//      materializes YJ, YK, BASE (= bias + S + Yi).
//   2) store_kernel: prologue overlaps kernel 1 under PDL; after the grid
//      dependency sync the loop is read-free: 8 FADD + 1 STG.256 per 32B.

#define M_DIM 96
#define D_DIM 16
#define S_DIM 16
#define N_DIM 4
#define PLANE (M_DIM * M_DIM)          // 9216 floats per (n,s,i) plane
#define NS (N_DIM * S_DIM)             // 64

__device__ float g_YJ[NS * M_DIM];
__device__ float g_YK[NS * M_DIM];
__device__ float g_BASE[NS * M_DIM];

__device__ __forceinline__ void stg256_cs(float* p,
                                          float a0, float a1, float a2, float a3,
                                          float a4, float a5, float a6, float a7) {
    asm volatile("st.global.cs.v8.f32 [%0], {%1,%2,%3,%4,%5,%6,%7,%8};"
                 :: "l"(p), "f"(a0), "f"(a1), "f"(a2), "f"(a3),
                    "f"(a4), "f"(a5), "f"(a6), "f"(a7)
                 : "memory");
}

// ---------------------------------------------------------------------------
// Kernel 1: per (n,s): Yb[m] = sum_d x[n,d,m] * c[d,s,b];
//           S = sum_d (sum_t x[n,d,t]) * c[d,s,3]
//           BASE[n,s,i] = bias[s] + S + Yi[i]
// ---------------------------------------------------------------------------
__global__ void precompute_kernel(const float* __restrict__ x,
                                  const float* __restrict__ coefs,
                                  const float* __restrict__ bias) {
    // Let the dependent store_kernel launch its prologue NOW; its
    // cudaGridDependencySynchronize() still waits for our completion.
    cudaTriggerProgrammaticLaunchCompletion();

    const int ns = blockIdx.x;          // n*S_DIM + s
    const int s  = ns % S_DIM;
    const int n  = ns / S_DIM;
    const int t  = threadIdx.x;         // 0..95

    const float* __restrict__ xn = x + (size_t)n * D_DIM * M_DIM;

    float yi = 0.f, yj = 0.f, yk = 0.f, yw = 0.f;
    #pragma unroll
    for (int d = 0; d < D_DIM; d++) {
        const float xv = xn[d * M_DIM + t];
        const float* __restrict__ c = coefs + d * S_DIM * 4 + s * 4;
        yi = fmaf(xv, c[0], yi);
        yj = fmaf(xv, c[1], yj);
        yk = fmaf(xv, c[2], yk);
        yw = fmaf(xv, c[3], yw);
    }

    const int idx = ns * M_DIM + t;
    g_YJ[idx] = yj;
    g_YK[idx] = yk;

    // Block-reduce yw over 96 threads (3 warps) -> S
    __shared__ float red[3];
    #pragma unroll
    for (int o = 16; o > 0; o >>= 1)
        yw += __shfl_down_sync(0xffffffffu, yw, o);
    if ((t & 31) == 0) red[t >> 5] = yw;
    __syncthreads();
    const float S = red[0] + red[1] + red[2];

    g_BASE[idx] = bias[s] + S + yi;
}

// ---------------------------------------------------------------------------
// Kernel 2: one block per (n,s,i) plane. 192 threads = 12 k8-groups x 16 j-rows.
// Thread keeps vk[8] = base + Yk[k8..k8+7] and its 6 yj values in registers;
// loop body is 8 FADD + 1 STG.256 (streaming).
// ---------------------------------------------------------------------------
__global__ __launch_bounds__(192)
void store_kernel(float* __restrict__ out) {
    const int bid = blockIdx.x;         // n*S*M + s*M + i
    const int i   = bid % M_DIM;
    const int ns  = bid / M_DIM;        // n*S + s
    const int t   = threadIdx.x;
    const int kg  = t % 12;             // k8 = kg*8
    const int jb  = t / 12;             // 0..15

    float* __restrict__ op = out + (size_t)bid * PLANE + kg * 8;

    __shared__ float yjs[M_DIM];

    // Wait for precompute_kernel's writes to be visible.
    cudaGridDependencySynchronize();

    const float4* __restrict__ YJ4 =
        reinterpret_cast<const float4*>(g_YJ + ns * M_DIM);
    const float4* __restrict__ YK4 =
        reinterpret_cast<const float4*>(g_YK + ns * M_DIM);

    if (t < 24) reinterpret_cast<float4*>(yjs)[t] = YJ4[t];

    const float  base = g_BASE[ns * M_DIM + i];   // warp-broadcast LDG
    const float4 ka   = YK4[kg * 2 + 0];
    const float4 kb   = YK4[kg * 2 + 1];
    float vk[8];
    vk[0] = base + ka.x;  vk[1] = base + ka.y;
    vk[2] = base + ka.z;  vk[3] = base + ka.w;
    vk[4] = base + kb.x;  vk[5] = base + kb.y;
    vk[6] = base + kb.z;  vk[7] = base + kb.w;

    __syncthreads();

    // Hoist this thread's 6 yj values into registers (batched LDS, full MLP).
    float yj[6];
    #pragma unroll
    for (int p = 0; p < 6; p++) yj[p] = yjs[jb + 16 * p];

    // Pure compute+store loop: 8 FADD + 1 STG.256 per iteration.
    #pragma unroll
    for (int p = 0; p < 6; p++) {
        const int j = jb + 16 * p;
        const float y = yj[p];
        stg256_cs(op + j * M_DIM,
                  vk[0] + y, vk[1] + y, vk[2] + y, vk[3] + y,
                  vk[4] + y, vk[5] + y, vk[6] + y, vk[7] + y);
    }
}

extern "C" void kernel_launch(void* const* d_in, const int* in_sizes, int n_in,
                              void* d_out, int out_size) {
    const float* x     = (const float*)d_in[0];
    const float* coefs = (const float*)d_in[1];
    const float* bias  = (const float*)d_in[2];
    float* out = (float*)d_out;

    precompute_kernel<<<NS, M_DIM>>>(x, coefs, bias);

    // PDL launch: store_kernel's prologue overlaps precompute_kernel.
    cudaLaunchConfig_t cfg = {};
    cfg.gridDim  = dim3(N_DIM * S_DIM * M_DIM);
    cfg.blockDim = dim3(192);
    cfg.dynamicSmemBytes = 0;
    cfg.stream = 0;
    cudaLaunchAttribute attrs[1];
    attrs[0].id = cudaLaunchAttributeProgrammaticStreamSerialization;
    attrs[0].val.programmaticStreamSerializationAllowed = 1;
    cfg.attrs = attrs;
    cfg.numAttrs = 1;
    cudaLaunchKernelEx(&cfg, store_kernel, out);
}

// round 8
// speedup vs baseline: 1.0793x; 1.0793x over previous
#include <cuda_runtime.h>
#include <cstddef>

// Eq1to3: out[n,s,i,j,k] = Yi[n,s,i] + Yj[n,s,j] + Yk[n,s,k] + S[n,s] + bias[s]
//
// Fused single-kernel producer/consumer:
//   blocks 0..63   : producer for ns=bid. 192 threads (two 96-thread halves)
//                    compute YJ/YK (half 1) and BASE = bias+S+Yi (half 2),
//                    then release a per-ns flag.
//   blocks 64..6207: one (n,s,i) output plane each. Acquire the ns flag
//                    (nanosleep backoff), then the proven read-free store
//                    loop: 4 FADD + 1 STG.128 (streaming) per float4.
// The store phase is at the chip write-path ceiling (~6.5 TB/s); this round
// only removes the second kernel launch + shortens the producer.

#define M_DIM 96
#define D_DIM 16
#define S_DIM 16
#define N_DIM 4
#define PLANE (M_DIM * M_DIM)          // 9216 floats per (n,s,i) plane
#define NS (N_DIM * S_DIM)             // 64
#define NPLANES (NS * M_DIM)           // 6144

__device__ float g_YJ[NS * M_DIM];     // ns*384B regions are 128B-line disjoint
__device__ float g_YK[NS * M_DIM];
__device__ float g_BASE[NS * M_DIM];
__device__ unsigned g_flags[NS];       // zero-init; monotone across replays

__global__ __launch_bounds__(192)
void eq1to3_fused(const float* __restrict__ x,
                  const float* __restrict__ coefs,
                  const float* __restrict__ bias,
                  float* __restrict__ out) {
    const int bid = blockIdx.x;
    const int t   = threadIdx.x;

    if (bid < NS) {
        // ---------------- Producer: ns = bid ----------------
        const int ns = bid;
        const int s  = ns % S_DIM;
        const int n  = ns / S_DIM;
        const int m  = t % M_DIM;            // column 0..95 (both halves)
        const bool low = (t < M_DIM);        // low: (yj,yk); high: (yi,yw)

        const float* __restrict__ xn = x + (size_t)n * D_DIM * M_DIM;
        const float* __restrict__ cs = coefs + s * 4;
        const int o1 = low ? 1 : 0;
        const int o2 = low ? 2 : 3;

        float a = 0.f, b = 0.f;
        #pragma unroll
        for (int d = 0; d < D_DIM; d++) {
            const float xv = xn[d * M_DIM + m];
            a = fmaf(xv, cs[d * 64 + o1], a);
            b = fmaf(xv, cs[d * 64 + o2], b);
        }

        const int idx = ns * M_DIM + m;
        __shared__ float red[3];
        __shared__ float yis[M_DIM];

        if (low) {
            g_YJ[idx] = a;                   // a = yj
            g_YK[idx] = b;                   // b = yk
        } else {
            yis[m] = a;                      // a = yi
            float yw = b;                    // b = yw, reduce over 96 threads
            #pragma unroll
            for (int o = 16; o > 0; o >>= 1)
                yw += __shfl_down_sync(0xffffffffu, yw, o);
            const int w = (t >> 5) - 3;      // warp 3,4,5 -> 0,1,2
            if ((t & 31) == 0) red[w] = yw;
        }
        __syncthreads();
        if (!low) {
            const float S = red[0] + red[1] + red[2];
            g_BASE[idx] = bias[s] + S + yis[m];
        }
        __threadfence();
        __syncthreads();
        if (t == 0) {
            asm volatile("st.release.gpu.global.u32 [%0], %1;"
                         :: "l"(&g_flags[ns]), "r"(1u) : "memory");
        }
        return;
    }

    // ---------------- Consumer: one (n,s,i) plane ----------------
    const int plane = bid - NS;             // n*S*M + s*M + i
    const int i   = plane % M_DIM;
    const int ns  = plane / M_DIM;
    const int kg  = t % 24;                 // k4 = kg*4
    const int jb  = t / 24;                 // 0..7

    float4* __restrict__ o4 =
        reinterpret_cast<float4*>(out + (size_t)plane * PLANE);

    __shared__ float yjs[M_DIM];

    // Acquire the producer's flag (throttled spin, thread 0 only).
    if (t == 0) {
        unsigned f;
        while (true) {
            asm volatile("ld.acquire.gpu.global.u32 %0, [%1];"
                         : "=r"(f) : "l"(&g_flags[ns]) : "memory");
            if (f) break;
            __nanosleep(64);
        }
    }
    __syncthreads();

    const float4* __restrict__ YJ4 =
        reinterpret_cast<const float4*>(g_YJ + ns * M_DIM);
    const float4* __restrict__ YK4 =
        reinterpret_cast<const float4*>(g_YK + ns * M_DIM);

    if (t < 24) reinterpret_cast<float4*>(yjs)[t] = YJ4[t];

    const float  base = g_BASE[ns * M_DIM + i];   // warp-broadcast LDG
    const float4 yk4  = YK4[kg];
    float4 vk;
    vk.x = base + yk4.x;
    vk.y = base + yk4.y;
    vk.z = base + yk4.z;
    vk.w = base + yk4.w;

    __syncthreads();

    // Hoist this thread's 12 yj values into registers (batched LDS, full MLP).
    float yj[12];
    #pragma unroll
    for (int p = 0; p < 12; p++) yj[p] = yjs[jb + 8 * p];

    // Pure compute+store loop: 4 FADD + 1 STG.128 (streaming) per iteration.
    #pragma unroll
    for (int p = 0; p < 12; p++) {
        const int j = jb + 8 * p;
        float4 v;
        v.x = vk.x + yj[p];
        v.y = vk.y + yj[p];
        v.z = vk.z + yj[p];
        v.w = vk.w + yj[p];
        __stcs(&o4[j * 24 + kg], v);
    }
}

extern "C" void kernel_launch(void* const* d_in, const int* in_sizes, int n_in,
                              void* d_out, int out_size) {
    const float* x     = (const float*)d_in[0];
    const float* coefs = (const float*)d_in[1];
    const float* bias  = (const float*)d_in[2];
    float* out = (float*)d_out;

    eq1to3_fused<<<NS + NPLANES, 192>>>(x, coefs, bias, out);
}